// round 2
// baseline (speedup 1.0000x reference)
#include <cuda_runtime.h>
#include <math.h>

#define NN 32768
#define NE 4096
#define NI 131072
#define DM 256
#define EPSV 1e-5f
#define NEGS 0.2f

// ------------------------- device scratch -------------------------
__device__ float g_h1[NN * DM];        // post bn1 node features
__device__ float g_xh[NN * 2 * DM];    // h1 @ attW^T  (reused as h3 output later)
__device__ float g_eattr[NE * DM];
__device__ float g_edge_out[NE * 2 * DM];
__device__ float g_hb[NN * DM];        // bn2(h1 + x2)
__device__ float g_sn[NN * 2];
__device__ float g_se[NE * 2];
__device__ float g_alpha[NI * 2];
__device__ float g_wn[2 * DM];
__device__ float g_we[2 * DM];
__device__ float g_dinv[NN];
__device__ int g_cnt_n[NN], g_off_n[NN + 1], g_cur_n[NN];
__device__ int g_cnt_e[NE], g_off_e[NE + 1], g_cur_e[NE];
__device__ int g_perm_n[NI], g_perm_e[NI];

__device__ __forceinline__ float leaky(float v) { return v >= 0.f ? v : NEGS * v; }

// ------------------------- CSR build -------------------------
__global__ void k_zero_int(int* a, int n) {
    int i = blockIdx.x * blockDim.x + threadIdx.x;
    if (i < n) a[i] = 0;
}

__global__ void k_hist(const int* __restrict__ idx_n, const int* __restrict__ idx_e) {
    int i = blockIdx.x * blockDim.x + threadIdx.x;
    if (i < NI) {
        atomicAdd(&g_cnt_n[idx_n[i]], 1);
        atomicAdd(&g_cnt_e[idx_e[i]], 1);
    }
}

// single-block exclusive scan (n <= 1024 * L)
__global__ void k_scan(const int* __restrict__ cnt, int* __restrict__ off,
                       int* __restrict__ cur, int n) {
    __shared__ int part[1024];
    int t = threadIdx.x;
    int L = (n + 1023) / 1024;
    int s = 0;
    for (int j = 0; j < L; j++) {
        int idx = t * L + j;
        if (idx < n) s += cnt[idx];
    }
    part[t] = s;
    __syncthreads();
    // Hillis-Steele inclusive scan
    for (int d = 1; d < 1024; d <<= 1) {
        int v = (t >= d) ? part[t - d] : 0;
        __syncthreads();
        part[t] += v;
        __syncthreads();
    }
    int run = (t == 0) ? 0 : part[t - 1];
    for (int j = 0; j < L; j++) {
        int idx = t * L + j;
        if (idx < n) {
            off[idx] = run;
            cur[idx] = run;
            run += cnt[idx];
        }
    }
    if (t == 1023) off[n] = run;
}

__global__ void k_scatter(const int* __restrict__ idx_n, const int* __restrict__ idx_e) {
    int i = blockIdx.x * blockDim.x + threadIdx.x;
    if (i < NI) {
        int p = atomicAdd(&g_cur_n[idx_n[i]], 1);
        g_perm_n[p] = i;
        int q = atomicAdd(&g_cur_e[idx_e[i]], 1);
        g_perm_e[q] = i;
    }
}

// ------------------------- contracted attention vectors -------------------------
// w_n[h][k] = sum_d attW[h*256+d][k] * att[h][d]
// w_e[h][k] = sum_d attW[h*256+d][k] * att[h][256+d]
__global__ void k_prepw(const float* __restrict__ attW, const float* __restrict__ att) {
    int t = threadIdx.x;       // 0..511
    int h = t / DM, k = t % DM;
    float accn = 0.f, acce = 0.f;
    for (int d = 0; d < DM; d++) {
        float w = attW[(h * DM + d) * DM + k];
        accn += w * att[h * 2 * DM + d];
        acce += w * att[h * 2 * DM + DM + d];
    }
    g_wn[t] = accn;
    g_we[t] = acce;
}

// ------------------------- GEMM: C[M,Nw] = A[M,256] @ W[Nw,256]^T -------------------------
// MODE 0: bn1(leaky(acc + bias))   MODE 1: raw   MODE 2: leaky(acc + bias)
template <int MODE>
__global__ void __launch_bounds__(256) k_gemm(
    const float* __restrict__ A, const float* __restrict__ W,
    float* __restrict__ C, int Nw,
    const float* __restrict__ bias,
    const float* __restrict__ bg, const float* __restrict__ bb,
    const float* __restrict__ bm, const float* __restrict__ bv) {
    __shared__ float As[32][68];
    __shared__ float Ws[32][68];
    int tid = threadIdx.x;
    int m0 = blockIdx.y * 64, n0 = blockIdx.x * 64;
    int lr = tid / 8;             // 0..31
    int lc = (tid % 8) * 4;       // 0..28
    int tm = (tid % 16) * 4;
    int tn = (tid / 16) * 4;

    float acc[4][4];
#pragma unroll
    for (int i = 0; i < 4; i++)
#pragma unroll
        for (int j = 0; j < 4; j++) acc[i][j] = 0.f;

    for (int k0 = 0; k0 < 256; k0 += 32) {
#pragma unroll
        for (int r = 0; r < 2; r++) {
            float4 av = *(const float4*)&A[(size_t)(m0 + lr + r * 32) * 256 + k0 + lc];
            As[lc + 0][lr + r * 32] = av.x;
            As[lc + 1][lr + r * 32] = av.y;
            As[lc + 2][lr + r * 32] = av.z;
            As[lc + 3][lr + r * 32] = av.w;
            float4 wv = *(const float4*)&W[(size_t)(n0 + lr + r * 32) * 256 + k0 + lc];
            Ws[lc + 0][lr + r * 32] = wv.x;
            Ws[lc + 1][lr + r * 32] = wv.y;
            Ws[lc + 2][lr + r * 32] = wv.z;
            Ws[lc + 3][lr + r * 32] = wv.w;
        }
        __syncthreads();
#pragma unroll
        for (int k = 0; k < 32; k++) {
            float4 a = *(const float4*)&As[k][tm];
            float4 w = *(const float4*)&Ws[k][tn];
            float af[4] = {a.x, a.y, a.z, a.w};
            float wf[4] = {w.x, w.y, w.z, w.w};
#pragma unroll
            for (int i = 0; i < 4; i++)
#pragma unroll
                for (int j = 0; j < 4; j++) acc[i][j] += af[i] * wf[j];
        }
        __syncthreads();
    }

#pragma unroll
    for (int i = 0; i < 4; i++) {
        int m = m0 + tm + i;
#pragma unroll
        for (int j = 0; j < 4; j++) {
            int n = n0 + tn + j;
            float v = acc[i][j];
            if (MODE == 0) {
                v = leaky(v + bias[n]);
                v = bg[n] * (v - bm[n]) * rsqrtf(bv[n] + EPSV) + bb[n];
            } else if (MODE == 2) {
                v = leaky(v + bias[n]);
            }
            C[(size_t)m * Nw + n] = v;
        }
    }
}

// ------------------------- edge feature aggregation -------------------------
__global__ void k_eattr(const int* __restrict__ idx_n) {
    int e = blockIdx.x;
    int d = threadIdx.x;   // 256
    int s = g_off_e[e], t = g_off_e[e + 1];
    float acc = 0.f;
    for (int j = s; j < t; j++) {
        int n = idx_n[g_perm_e[j]];
        acc += g_h1[(size_t)n * DM + d];
    }
    g_eattr[(size_t)e * DM + d] = acc;
}

// ------------------------- per-row 2-head dot: out[r][h] = X[r,:]·Wv[h,:] -------------------------
__global__ void k_dot(const float* __restrict__ X, const float* __restrict__ Wv,
                      float* __restrict__ out, int rows) {
    int gw = (blockIdx.x * blockDim.x + threadIdx.x) / 32;
    int lane = threadIdx.x & 31;
    if (gw >= rows * 2) return;
    int r = gw / 2, h = gw % 2;
    float acc = 0.f;
    for (int k = lane; k < DM; k += 32) acc += X[(size_t)r * DM + k] * Wv[h * DM + k];
#pragma unroll
    for (int o = 16; o > 0; o >>= 1) acc += __shfl_down_sync(0xffffffffu, acc, o);
    if (lane == 0) out[r * 2 + h] = acc;
}

// ------------------------- per-node segment softmax -------------------------
__global__ void k_softmax(const int* __restrict__ idx_e) {
    int n = blockIdx.x * blockDim.x + threadIdx.x;
    if (n >= NN) return;
    int s = g_off_n[n], t = g_off_n[n + 1];
    int deg = t - s;
    g_dinv[n] = deg > 0 ? 1.0f / (float)deg : 0.0f;
    if (deg == 0) return;
    float sn0 = g_sn[n * 2], sn1 = g_sn[n * 2 + 1];
    float m0 = -3.402823e38f, m1 = -3.402823e38f;
    for (int j = s; j < t; j++) {
        int i = g_perm_n[j];
        int e = idx_e[i];
        float a0 = leaky(sn0 + g_se[e * 2]);
        float a1 = leaky(sn1 + g_se[e * 2 + 1]);
        m0 = fmaxf(m0, a0);
        m1 = fmaxf(m1, a1);
    }
    float d0 = 0.f, d1 = 0.f;
    for (int j = s; j < t; j++) {
        int i = g_perm_n[j];
        int e = idx_e[i];
        float e0 = expf(leaky(sn0 + g_se[e * 2]) - m0);
        float e1 = expf(leaky(sn1 + g_se[e * 2 + 1]) - m1);
        d0 += e0;
        d1 += e1;
        g_alpha[i * 2] = e0;
        g_alpha[i * 2 + 1] = e1;
    }
    float r0 = 1.0f / (d0 + 1e-16f);
    float r1 = 1.0f / (d1 + 1e-16f);
    for (int j = s; j < t; j++) {
        int i = g_perm_n[j];
        g_alpha[i * 2] *= r0;
        g_alpha[i * 2 + 1] *= r1;
    }
}

// ------------------------- edge_out[e,h,d] = Binv * sum alpha * xh[n,h,d] -------------------------
__global__ void __launch_bounds__(512) k_edgeout(const int* __restrict__ idx_n) {
    int e = blockIdx.x;
    int t = threadIdx.x;   // 512 : h*256 + d
    int h = t >> 8;
    int s = g_off_e[e], en = g_off_e[e + 1];
    float binv = (en > s) ? 1.0f / (float)(en - s) : 0.0f;
    float acc = 0.f;
    for (int j = s; j < en; j++) {
        int i = g_perm_e[j];
        int n = idx_n[i];
        acc += g_alpha[i * 2 + h] * g_xh[(size_t)n * 512 + t];
    }
    g_edge_out[(size_t)e * 512 + t] = binv * acc;
}

// ------------------------- node_out + mean heads + cb + bn2 -------------------------
__global__ void __launch_bounds__(256) k_nodeout(
    const int* __restrict__ idx_e, const float* __restrict__ cb,
    const float* __restrict__ g2, const float* __restrict__ b2,
    const float* __restrict__ m2, const float* __restrict__ v2) {
    int n = blockIdx.x;
    int d = threadIdx.x;   // 256
    int s = g_off_n[n], t = g_off_n[n + 1];
    float acc0 = 0.f, acc1 = 0.f;
    for (int j = s; j < t; j++) {
        int i = g_perm_n[j];
        int e = idx_e[i];
        acc0 += g_alpha[i * 2] * g_edge_out[(size_t)e * 512 + d];
        acc1 += g_alpha[i * 2 + 1] * g_edge_out[(size_t)e * 512 + 256 + d];
    }
    float x2 = g_dinv[n] * 0.5f * (acc0 + acc1) + cb[d];
    float v = g_h1[(size_t)n * DM + d] + x2;
    v = g2[d] * (v - m2[d]) * rsqrtf(v2[d] + EPSV) + b2[d];
    g_hb[(size_t)n * DM + d] = v;
}

// ------------------------- residual + LayerNorm over 64-chunks -------------------------
__global__ void k_ln(const float* __restrict__ x, const float* __restrict__ h3,
                     const float* __restrict__ lg, const float* __restrict__ lb,
                     float* __restrict__ out) {
    int g = (blockIdx.x * blockDim.x + threadIdx.x) >> 5;   // one warp per 64-group
    int lane = threadIdx.x & 31;
    if (g >= NI) return;   // NI == 131072 groups
    size_t base = (size_t)g * 64;
    float y0 = x[base + lane] + h3[base + lane];
    float y1 = x[base + 32 + lane] + h3[base + 32 + lane];
    float s = y0 + y1;
#pragma unroll
    for (int o = 16; o > 0; o >>= 1) s += __shfl_xor_sync(0xffffffffu, s, o);
    float mu = s * (1.0f / 64.0f);
    float d0 = y0 - mu, d1 = y1 - mu;
    float vv = d0 * d0 + d1 * d1;
#pragma unroll
    for (int o = 16; o > 0; o >>= 1) vv += __shfl_xor_sync(0xffffffffu, vv, o);
    float rs = rsqrtf(vv * (1.0f / 64.0f) + EPSV);
    out[base + lane] = lg[lane] * d0 * rs + lb[lane];
    out[base + 32 + lane] = lg[lane + 32] * d1 * rs + lb[lane + 32];
}

// ------------------------- launch -------------------------
extern "C" void kernel_launch(void* const* d_in, const int* in_sizes, int n_in,
                              void* d_out, int out_size) {
    const float* x    = (const float*)d_in[0];
    const int*   he   = (const int*)d_in[1];
    const int*   idx_n = he;
    const int*   idx_e = he + NI;
    const float* W1   = (const float*)d_in[2];
    const float* b1   = (const float*)d_in[3];
    const float* bn1g = (const float*)d_in[4];
    const float* bn1b = (const float*)d_in[5];
    const float* bn1m = (const float*)d_in[6];
    const float* bn1v = (const float*)d_in[7];
    const float* attW = (const float*)d_in[8];
    const float* att  = (const float*)d_in[9];
    const float* cb   = (const float*)d_in[10];
    const float* bn2g = (const float*)d_in[11];
    const float* bn2b = (const float*)d_in[12];
    const float* bn2m = (const float*)d_in[13];
    const float* bn2v = (const float*)d_in[14];
    const float* W2   = (const float*)d_in[15];
    const float* b2   = (const float*)d_in[16];
    const float* lng  = (const float*)d_in[17];
    const float* lnb  = (const float*)d_in[18];
    float* out = (float*)d_out;

    float *p_h1, *p_xh, *p_eattr, *p_hb, *p_sn, *p_se, *p_wn, *p_we;
    int *p_cnt_n, *p_cnt_e, *p_off_n, *p_off_e, *p_cur_n, *p_cur_e;
    cudaGetSymbolAddress((void**)&p_h1, g_h1);
    cudaGetSymbolAddress((void**)&p_xh, g_xh);
    cudaGetSymbolAddress((void**)&p_eattr, g_eattr);
    cudaGetSymbolAddress((void**)&p_hb, g_hb);
    cudaGetSymbolAddress((void**)&p_sn, g_sn);
    cudaGetSymbolAddress((void**)&p_se, g_se);
    cudaGetSymbolAddress((void**)&p_wn, g_wn);
    cudaGetSymbolAddress((void**)&p_we, g_we);
    cudaGetSymbolAddress((void**)&p_cnt_n, g_cnt_n);
    cudaGetSymbolAddress((void**)&p_cnt_e, g_cnt_e);
    cudaGetSymbolAddress((void**)&p_off_n, g_off_n);
    cudaGetSymbolAddress((void**)&p_off_e, g_off_e);
    cudaGetSymbolAddress((void**)&p_cur_n, g_cur_n);
    cudaGetSymbolAddress((void**)&p_cur_e, g_cur_e);

    // ---- CSR build ----
    k_zero_int<<<(NN + 255) / 256, 256>>>(p_cnt_n, NN);
    k_zero_int<<<(NE + 255) / 256, 256>>>(p_cnt_e, NE);
    k_hist<<<(NI + 255) / 256, 256>>>(idx_n, idx_e);
    k_scan<<<1, 1024>>>(p_cnt_n, p_off_n, p_cur_n, NN);
    k_scan<<<1, 1024>>>(p_cnt_e, p_off_e, p_cur_e, NE);
    k_scatter<<<(NI + 255) / 256, 256>>>(idx_n, idx_e);

    // ---- contracted attention weight vectors ----
    k_prepw<<<1, 512>>>(attW, att);

    // ---- GEMM 1: h1 = bn1(leaky(x @ W1^T + b1)) ----
    {
        dim3 grid(DM / 64, NN / 64);
        k_gemm<0><<<grid, 256>>>(x, W1, p_h1, DM, b1, bn1g, bn1b, bn1m, bn1v);
    }

    // ---- edge features + scores ----
    k_eattr<<<NE, 256>>>(idx_n);
    k_dot<<<(NN * 2 * 32 + 255) / 256, 256>>>(p_h1, p_wn, p_sn, NN);
    k_dot<<<(NE * 2 * 32 + 255) / 256, 256>>>(p_eattr, p_we, p_se, NE);

    // ---- GEMM 2: xh = h1 @ attW^T  [NN, 512] ----
    {
        dim3 grid(512 / 64, NN / 64);
        k_gemm<1><<<grid, 256>>>(p_h1, attW, p_xh, 512, nullptr, nullptr, nullptr, nullptr, nullptr);
    }

    // ---- segment softmax ----
    k_softmax<<<(NN + 255) / 256, 256>>>(idx_e);

    // ---- message passing ----
    k_edgeout<<<NE, 512>>>(idx_n);
    k_nodeout<<<NN, 256>>>(idx_e, cb, bn2g, bn2b, bn2m, bn2v);

    // ---- GEMM 3: h3 = leaky(hb @ W2^T + b2)  (reuse g_xh as h3) ----
    {
        dim3 grid(DM / 64, NN / 64);
        k_gemm<2><<<grid, 256>>>(p_hb, W2, p_xh, DM, b2, nullptr, nullptr, nullptr, nullptr);
    }

    // ---- residual + LayerNorm ----
    k_ln<<<(NI * 32 + 255) / 256, 256>>>(x, p_xh, lng, lnb, out);
}